// round 1
// baseline (speedup 1.0000x reference)
#include <cuda_runtime.h>

// ---------------- scratch (static device globals; no allocation) ----------------
__device__ float g_h1[8388608];   // [32][64][64][64]  conv1+pool out, NHWC
__device__ float g_f[4194304];    // [32][32][32][128] conv2+pool out, NHWC
__device__ float g_q[2097152];    // [b*4+n][y][x][16]
__device__ float g_k[2097152];
__device__ float g_v[2097152];
__device__ float g_o[2097152];    // [b][y][x][64]
__device__ float g_pooled[4096];  // [32][128]

// ---------------- conv1 (3->64) + relu + maxpool2 ----------------
__global__ __launch_bounds__(256) void conv1_pool_k(const float* __restrict__ x,
                                                    const float* __restrict__ w,
                                                    const float* __restrict__ bias) {
  __shared__ float sw[1728];
  __shared__ float sb[64];
  for (int i = threadIdx.x; i < 1728; i += 256) sw[i] = w[i];
  if (threadIdx.x < 64) sb[threadIdx.x] = bias[threadIdx.x];
  __syncthreads();
  int idx = blockIdx.x * 256 + threadIdx.x;        // (b,py,px) pooled pixel
  int px = idx & 63, py = (idx >> 6) & 63, b = idx >> 12;

  float in[3][4][4];
#pragma unroll
  for (int c = 0; c < 3; c++) {
#pragma unroll
    for (int r = 0; r < 4; r++) {
      int iy = 2 * py - 1 + r;
      bool yok = (iy >= 0 && iy < 128);
      const float* xr = x + ((size_t)(b * 3 + c) * 128 + (yok ? iy : 0)) * 128;
#pragma unroll
      for (int cc = 0; cc < 4; cc++) {
        int ix = 2 * px - 1 + cc;
        in[c][r][cc] = (yok && ix >= 0 && ix < 128) ? xr[ix] : 0.f;
      }
    }
  }
  float* outp = &g_h1[(size_t)idx * 64];
  float4 vbuf;
  float* vb = (float*)&vbuf;
  for (int oc = 0; oc < 64; oc++) {
    float bsv = sb[oc];
    float a0 = bsv, a1 = bsv, a2 = bsv, a3 = bsv;
    const float* wp = &sw[oc * 27];
#pragma unroll
    for (int c = 0; c < 3; c++)
#pragma unroll
      for (int kh = 0; kh < 3; kh++)
#pragma unroll
        for (int kw = 0; kw < 3; kw++) {
          float wv = wp[c * 9 + kh * 3 + kw];
          a0 += in[c][kh][kw] * wv;
          a1 += in[c][kh][kw + 1] * wv;
          a2 += in[c][kh + 1][kw] * wv;
          a3 += in[c][kh + 1][kw + 1] * wv;
        }
    float m = fmaxf(fmaxf(a0, a1), fmaxf(a2, a3));
    vb[oc & 3] = fmaxf(m, 0.f);
    if ((oc & 3) == 3) ((float4*)outp)[oc >> 2] = vbuf;
  }
}

// ---------------- conv2 (64->128) + relu + maxpool2 ----------------
// block: 512 threads = 32 pixels (8x4 pooled tile) x 16 oc-groups (8 oc each)
__global__ __launch_bounds__(512) void conv2_pool_k(const float* __restrict__ w,
                                                    const float* __restrict__ bias) {
  __shared__ float s_in[180 * 33];  // [(row*18+col)][c], 10 rows x 18 cols x 32 ch, pad 33
  int b = blockIdx.x >> 5;
  int tile = blockIdx.x & 31;
  int ty0 = (tile >> 2) * 4;
  int tx0 = (tile & 3) * 8;
  int tid = threadIdx.x;
  int pix = tid & 31;
  int px = pix & 7, py = pix >> 3;
  int oc0 = (tid >> 5) * 8;

  float acc[8][4];
#pragma unroll
  for (int o = 0; o < 8; o++) {
    float bv = bias[oc0 + o];
#pragma unroll
    for (int p = 0; p < 4; p++) acc[o][p] = bv;
  }

  for (int ic0 = 0; ic0 < 64; ic0 += 32) {
    __syncthreads();
    for (int i = tid; i < 180 * 32; i += 512) {
      int c = i & 31;
      int rc = i >> 5;
      int row = rc / 18, col = rc - row * 18;
      int iy = 2 * ty0 - 1 + row;
      int ix = 2 * tx0 - 1 + col;
      float val = 0.f;
      if (iy >= 0 && iy < 64 && ix >= 0 && ix < 64)
        val = g_h1[((size_t)(b * 64 + iy) * 64 + ix) * 64 + ic0 + c];
      s_in[rc * 33 + c] = val;
    }
    __syncthreads();
#pragma unroll 2
    for (int ic = 0; ic < 32; ic++) {
      float iv[4][4];
#pragma unroll
      for (int r = 0; r < 4; r++)
#pragma unroll
        for (int cc = 0; cc < 4; cc++)
          iv[r][cc] = s_in[((2 * py + r) * 18 + 2 * px + cc) * 33 + ic];
      const float* wb = w + (size_t)(ic0 + ic) * 9;
#pragma unroll
      for (int kh = 0; kh < 3; kh++)
#pragma unroll
        for (int kw = 0; kw < 3; kw++) {
          int woff = kh * 3 + kw;
#pragma unroll
          for (int o = 0; o < 8; o++) {
            float wv = __ldg(wb + (size_t)(oc0 + o) * 576 + woff);
            acc[o][0] += iv[kh][kw] * wv;
            acc[o][1] += iv[kh][kw + 1] * wv;
            acc[o][2] += iv[kh + 1][kw] * wv;
            acc[o][3] += iv[kh + 1][kw + 1] * wv;
          }
        }
    }
  }
  int y = ty0 + py, xo = tx0 + px;
  float* outp = &g_f[((size_t)(b * 32 + y) * 32 + xo) * 128 + oc0];
  float res[8];
#pragma unroll
  for (int o = 0; o < 8; o++) {
    float m = fmaxf(fmaxf(acc[o][0], acc[o][1]), fmaxf(acc[o][2], acc[o][3]));
    res[o] = fmaxf(m, 0.f);
  }
  ((float4*)outp)[0] = make_float4(res[0], res[1], res[2], res[3]);
  ((float4*)outp)[1] = make_float4(res[4], res[5], res[6], res[7]);
}

// ---------------- fused Q/K/V projection (tiled GEMM, grid.y selects q/k/v) ----------------
__global__ __launch_bounds__(256) void qkv_k(const float* __restrict__ qw, const float* __restrict__ qb,
                                             const float* __restrict__ kw, const float* __restrict__ kb,
                                             const float* __restrict__ vw, const float* __restrict__ vb) {
  __shared__ float As[64 * 33];
  __shared__ float Bs[64 * 33];
  int which = blockIdx.y;
  const float* W = which == 0 ? qw : (which == 1 ? kw : vw);
  const float* bi = which == 0 ? qb : (which == 1 ? kb : vb);
  float* dst = which == 0 ? g_q : (which == 1 ? g_k : g_v);
  float scale = which == 0 ? 0.25f : 1.0f;
  int m0 = blockIdx.x * 64;
  int tid = threadIdx.x;
  int tx = tid & 15, ty = tid >> 4;
  float acc[4][4] = {};
  for (int k0 = 0; k0 < 128; k0 += 32) {
    __syncthreads();
#pragma unroll
    for (int t = 0; t < 8; t++) {
      int i = tid + t * 256;
      int kk = i & 31, r = i >> 5;
      As[r * 33 + kk] = g_f[(size_t)(m0 + r) * 128 + k0 + kk];
      Bs[r * 33 + kk] = W[(size_t)r * 128 + k0 + kk];
    }
    __syncthreads();
#pragma unroll
    for (int kk = 0; kk < 32; kk++) {
      float a[4], bv[4];
#pragma unroll
      for (int i = 0; i < 4; i++) a[i] = As[(ty * 4 + i) * 33 + kk];
#pragma unroll
      for (int j = 0; j < 4; j++) bv[j] = Bs[(tx * 4 + j) * 33 + kk];
#pragma unroll
      for (int i = 0; i < 4; i++)
#pragma unroll
        for (int j = 0; j < 4; j++) acc[i][j] += a[i] * bv[j];
    }
  }
#pragma unroll
  for (int i = 0; i < 4; i++) {
    int m = m0 + ty * 4 + i;
    int bimg = m >> 10, y = (m >> 5) & 31, xx = m & 31;
#pragma unroll
    for (int j = 0; j < 4; j++) {
      int col = tx * 4 + j;
      int n = col >> 4, d = col & 15;
      float val = (acc[i][j] + bi[col]) * scale;
      dst[((size_t)(bimg * 4 + n) * 1024 + y * 32 + xx) * 16 + d] = val;
    }
  }
}

// ---------------- axial attention: one warp per (b,head,line); lane = query ----------------
__global__ __launch_bounds__(256) void attn_k(const float* __restrict__ rel, int is_col) {
  __shared__ float sk[8][512];
  __shared__ float sv[8][512];
  __shared__ float srel[252];
  int tid = threadIdx.x;
  for (int i = tid; i < 252; i += 256) srel[i] = rel[i];
  int w = tid >> 5, lane = tid & 31;
  int r = blockIdx.x * 8 + w;
  int fixed = r & 31;   // y for row-attn, x for col-attn
  int bn = r >> 5;      // b*4 + head
  int n = bn & 3, bimg = bn >> 2;

  if (!is_col) {
    const float* kb = &g_k[(size_t)(bn * 32 + fixed) * 512];
    const float* vbp = &g_v[(size_t)(bn * 32 + fixed) * 512];
    for (int i = lane; i < 512; i += 32) { sk[w][i] = kb[i]; sv[w][i] = vbp[i]; }
  } else {
    for (int i = lane; i < 512; i += 32) {
      int j = i >> 4, d = i & 15;
      size_t off = ((size_t)(bn * 32 + j) * 32 + fixed) * 16 + d;
      sk[w][i] = g_k[off]; sv[w][i] = g_v[off];
    }
  }
  __syncthreads();

  size_t qoff = is_col ? (((size_t)(bn * 32 + lane) * 32 + fixed) * 16)
                       : (((size_t)(bn * 32 + fixed) * 32 + lane) * 16);
  float q[16];
#pragma unroll
  for (int d = 0; d < 16; d++) q[d] = g_q[qoff + d];

  const float* rl = &srel[n * 63 + lane + 31];  // bias(i=lane, j) = rl[-j]
  float s[32];
  float mx = -1e30f;
#pragma unroll
  for (int j = 0; j < 32; j++) {
    float a = rl[-j];
#pragma unroll
    for (int d = 0; d < 16; d++) a += q[d] * sk[w][j * 16 + d];
    s[j] = a;
    mx = fmaxf(mx, a);
  }
  float sum = 0.f;
#pragma unroll
  for (int j = 0; j < 32; j++) { s[j] = __expf(s[j] - mx); sum += s[j]; }
  float inv = 1.f / sum;
  float o[16];
#pragma unroll
  for (int d = 0; d < 16; d++) o[d] = 0.f;
#pragma unroll
  for (int j = 0; j < 32; j++) {
    float p = s[j];
#pragma unroll
    for (int d = 0; d < 16; d++) o[d] += p * sv[w][j * 16 + d];
  }
  size_t ooff = is_col ? (((size_t)(bimg * 32 + lane) * 32 + fixed) * 64 + n * 16)
                       : (((size_t)(bimg * 32 + fixed) * 32 + lane) * 64 + n * 16);
  if (!is_col) {
#pragma unroll
    for (int d = 0; d < 16; d++) g_o[ooff + d] = o[d] * inv;
  } else {
#pragma unroll
    for (int d = 0; d < 16; d++) g_o[ooff + d] += o[d] * inv;
  }
}

// ---------------- projection + residual + mean pool ----------------
__global__ void zero_pooled_k() {
  int i = blockIdx.x * blockDim.x + threadIdx.x;
  if (i < 4096) g_pooled[i] = 0.f;
}

__global__ __launch_bounds__(128) void proj_pool_k(const float* __restrict__ pw) {
  int b = blockIdx.x >> 3, chunk = blockIdx.x & 7;
  int c = threadIdx.x;
  float wreg[64];
#pragma unroll
  for (int d = 0; d < 64; d++) wreg[d] = pw[c * 64 + d];
  __shared__ float so[64];
  float acc = 0.f;
  int p0 = chunk * 128;
  for (int p = p0; p < p0 + 128; p++) {
    __syncthreads();
    if (c < 64) so[c] = g_o[((size_t)b * 1024 + p) * 64 + c];
    __syncthreads();
    float t = g_f[((size_t)b * 1024 + p) * 128 + c];
#pragma unroll
    for (int d = 0; d < 64; d++) t += so[d] * wreg[d];
    acc += t;
  }
  atomicAdd(&g_pooled[b * 128 + c], acc);
}

__global__ void fc_k(const float* __restrict__ pb, const float* __restrict__ fw,
                     const float* __restrict__ fb, float* __restrict__ out) {
  int idx = threadIdx.x;
  if (idx >= 320) return;
  int b = idx / 10, j = idx - b * 10;
  float acc = fb[j];
  for (int c = 0; c < 128; c++)
    acc += (g_pooled[b * 128 + c] * (1.f / 1024.f) + pb[c]) * fw[j * 128 + c];
  out[idx] = acc;
}

// ---------------- launch ----------------
extern "C" void kernel_launch(void* const* d_in, const int* in_sizes, int n_in,
                              void* d_out, int out_size) {
  const float* x   = (const float*)d_in[0];
  const float* c1w = (const float*)d_in[1];
  const float* c1b = (const float*)d_in[2];
  const float* c2w = (const float*)d_in[3];
  const float* c2b = (const float*)d_in[4];
  const float* qw  = (const float*)d_in[5];
  const float* qb  = (const float*)d_in[6];
  const float* kw  = (const float*)d_in[7];
  const float* kb  = (const float*)d_in[8];
  const float* vw  = (const float*)d_in[9];
  const float* vb  = (const float*)d_in[10];
  const float* pw  = (const float*)d_in[11];
  const float* pb  = (const float*)d_in[12];
  const float* rh  = (const float*)d_in[13];
  const float* rw  = (const float*)d_in[14];
  const float* fw  = (const float*)d_in[15];
  const float* fb  = (const float*)d_in[16];
  float* out = (float*)d_out;

  conv1_pool_k<<<512, 256>>>(x, c1w, c1b);
  conv2_pool_k<<<1024, 512>>>(c2w, c2b);
  qkv_k<<<dim3(512, 3), 256>>>(qw, qb, kw, kb, vw, vb);
  attn_k<<<512, 256>>>(rw, 0);
  attn_k<<<512, 256>>>(rh, 1);
  zero_pooled_k<<<4, 1024>>>();
  proj_pool_k<<<256, 128>>>(pw);
  fc_k<<<1, 320>>>(pb, fw, fb, out);
}